// round 1
// baseline (speedup 1.0000x reference)
#include <cuda_runtime.h>
#include <math.h>

#define BATCH 4
#define LSEQ  2048
#define NHEAD 16
#define DK    64
#define NF    1024
#define MTOT  (BATCH * LSEQ)   // 8192

// Scratch (device globals: no allocations allowed in kernel_launch)
__device__ float g_q[(size_t)BATCH * NHEAD * LSEQ * DK];
__device__ float g_k[(size_t)BATCH * NHEAD * LSEQ * DK];
__device__ float g_v[(size_t)BATCH * NHEAD * LSEQ * DK];
__device__ float g_x[(size_t)MTOT * NF];

// ---------------------------------------------------------------------------
// SGEMM: C[M=8192, N=1024] = A[8192,1024] @ W[1024,1024] + bias
// mode 0: C row-major [m][n]
// mode 1: scatter to [b*16+h][l][d] layout (b=m>>11, l=m&2047, h=n>>6, d=n&63)
// 128x128x16 tile, 256 threads, 8x8 per-thread register tile.
// ---------------------------------------------------------------------------
__global__ __launch_bounds__(256) void gemm_bias_kernel(
    const float* __restrict__ A, const float* __restrict__ W,
    const float* __restrict__ bias, float* __restrict__ C, int mode)
{
    __shared__ float As[16][129];   // A transposed: As[k][row], pad -> conflict-free
    __shared__ float Ws[16][128];   // Ws[k][n]

    const int tid = threadIdx.x;
    const int tx = tid & 15;
    const int ty = tid >> 4;
    const int m0 = blockIdx.y * 128;
    const int n0 = blockIdx.x * 128;

    const float4* A4 = (const float4*)A;
    const float4* W4 = (const float4*)W;

    float acc[8][8];
#pragma unroll
    for (int i = 0; i < 8; i++)
#pragma unroll
        for (int j = 0; j < 8; j++) acc[i][j] = 0.f;

    float4 pa[2], pw[2];
    // prefetch kt = 0
#pragma unroll
    for (int s = 0; s < 2; s++) {
        int idx = tid + 256 * s;
        int ar = idx >> 2, kc = idx & 3;
        pa[s] = A4[(size_t)(m0 + ar) * (NF / 4) + kc];
        int wr = idx >> 5, nc = idx & 31;
        pw[s] = W4[(size_t)wr * (NF / 4) + (n0 >> 2) + nc];
    }

    const int NKT = NF / 16;   // 64
    for (int kt = 0; kt < NKT; kt++) {
        // store prefetched tile to smem
#pragma unroll
        for (int s = 0; s < 2; s++) {
            int idx = tid + 256 * s;
            int ar = idx >> 2, kc = idx & 3;
            As[kc * 4 + 0][ar] = pa[s].x;
            As[kc * 4 + 1][ar] = pa[s].y;
            As[kc * 4 + 2][ar] = pa[s].z;
            As[kc * 4 + 3][ar] = pa[s].w;
            int wr = idx >> 5, nc = idx & 31;
            ((float4*)(&Ws[wr][0]))[nc] = pw[s];
        }
        __syncthreads();

        if (kt + 1 < NKT) {
#pragma unroll
            for (int s = 0; s < 2; s++) {
                int idx = tid + 256 * s;
                int ar = idx >> 2, kc = idx & 3;
                pa[s] = A4[(size_t)(m0 + ar) * (NF / 4) + (kt + 1) * 4 + kc];
                int wr = idx >> 5, nc = idx & 31;
                pw[s] = W4[(size_t)((kt + 1) * 16 + wr) * (NF / 4) + (n0 >> 2) + nc];
            }
        }

#pragma unroll
        for (int k = 0; k < 16; k++) {
            float ra[8], rb[8];
#pragma unroll
            for (int i = 0; i < 8; i++) ra[i] = As[k][ty + 16 * i];
#pragma unroll
            for (int j = 0; j < 8; j++) rb[j] = Ws[k][tx + 16 * j];
#pragma unroll
            for (int i = 0; i < 8; i++)
#pragma unroll
                for (int j = 0; j < 8; j++) acc[i][j] += ra[i] * rb[j];
        }
        __syncthreads();
    }

    // epilogue
#pragma unroll
    for (int j = 0; j < 8; j++) {
        int n = n0 + tx + 16 * j;
        float bv = bias[n];
#pragma unroll
        for (int i = 0; i < 8; i++) {
            int m = m0 + ty + 16 * i;
            float v = acc[i][j] + bv;
            if (mode == 0) {
                C[(size_t)m * NF + n] = v;
            } else {
                int b = m >> 11, l = m & 2047;
                int h = n >> 6,  d = n & 63;
                C[(((size_t)(b * NHEAD + h)) * LSEQ + l) * DK + d] = v;
            }
        }
    }
}

// ---------------------------------------------------------------------------
// Flash attention, fp32. One block = one (b,h) x 64-query tile.
// 256 threads, 4x4 per-thread tile (rows r = ty+16i, cols c = tx+16j).
// Smem: Qs/Ks/Vs each [64][66]; P overwrites Ks between phases.
// ---------------------------------------------------------------------------
#define ST 66

__global__ __launch_bounds__(256) void attn_kernel(
    const float* __restrict__ Q, const float* __restrict__ K,
    const float* __restrict__ V, float* __restrict__ X)
{
    extern __shared__ float sm[];
    float* Qs = sm;                 // [64][ST]
    float* Ks = sm + 64 * ST;       // [64][ST], reused as P
    float* Vs = sm + 2 * 64 * ST;   // [64][ST]

    const int tid = threadIdx.x;
    const int tx = tid & 15;
    const int ty = tid >> 4;
    const int qt = blockIdx.x;      // query tile 0..31
    const int bh = blockIdx.y;      // 0..63

    const float* Qg = Q + ((size_t)bh * LSEQ + qt * 64) * DK;
    const float* Kg = K + (size_t)bh * LSEQ * DK;
    const float* Vg = V + (size_t)bh * LSEQ * DK;

    // load Q tile (64x64 floats) as float2, coalesced
    {
        const float2* Qg2 = (const float2*)Qg;
#pragma unroll
        for (int s = 0; s < 8; s++) {
            int idx = tid + 256 * s;
            int r = idx >> 5, c2 = idx & 31;
            float2 v = Qg2[r * 32 + c2];
            Qs[r * ST + c2 * 2]     = v.x;
            Qs[r * ST + c2 * 2 + 1] = v.y;
        }
    }

    float mrow[4], lrow[4], O[4][4];
#pragma unroll
    for (int i = 0; i < 4; i++) {
        mrow[i] = -1e30f;
        lrow[i] = 0.f;
#pragma unroll
        for (int j = 0; j < 4; j++) O[i][j] = 0.f;
    }

    const float scale = 0.125f;   // 1/sqrt(64)

    for (int kt = 0; kt < LSEQ / 64; kt++) {
        // load K, V tiles
        const float2* Kg2 = (const float2*)(Kg + (size_t)kt * 64 * DK);
        const float2* Vg2 = (const float2*)(Vg + (size_t)kt * 64 * DK);
#pragma unroll
        for (int s = 0; s < 8; s++) {
            int idx = tid + 256 * s;
            int r = idx >> 5, c2 = idx & 31;
            float2 kv = Kg2[r * 32 + c2];
            Ks[r * ST + c2 * 2]     = kv.x;
            Ks[r * ST + c2 * 2 + 1] = kv.y;
            float2 vv = Vg2[r * 32 + c2];
            Vs[r * ST + c2 * 2]     = vv.x;
            Vs[r * ST + c2 * 2 + 1] = vv.y;
        }
        __syncthreads();

        // S = Q K^T  (64x64 tile, 4x4 per thread)
        float s4[4][4];
#pragma unroll
        for (int i = 0; i < 4; i++)
#pragma unroll
            for (int j = 0; j < 4; j++) s4[i][j] = 0.f;

#pragma unroll 8
        for (int k = 0; k < DK; k++) {
            float qa[4], kb[4];
#pragma unroll
            for (int i = 0; i < 4; i++) qa[i] = Qs[(ty + 16 * i) * ST + k];
#pragma unroll
            for (int j = 0; j < 4; j++) kb[j] = Ks[(tx + 16 * j) * ST + k];
#pragma unroll
            for (int i = 0; i < 4; i++)
#pragma unroll
                for (int j = 0; j < 4; j++) s4[i][j] += qa[i] * kb[j];
        }

        // online softmax per row (reduce across 16 tx lanes, same warp half)
#pragma unroll
        for (int i = 0; i < 4; i++) {
            float tmax = -1e30f;
#pragma unroll
            for (int j = 0; j < 4; j++) {
                s4[i][j] *= scale;
                tmax = fmaxf(tmax, s4[i][j]);
            }
#pragma unroll
            for (int off = 8; off >= 1; off >>= 1)
                tmax = fmaxf(tmax, __shfl_xor_sync(0xffffffffu, tmax, off));
            float mn = fmaxf(mrow[i], tmax);
            float corr = __expf(mrow[i] - mn);
            float rs = 0.f;
#pragma unroll
            for (int j = 0; j < 4; j++) {
                float p = __expf(s4[i][j] - mn);
                s4[i][j] = p;
                rs += p;
            }
#pragma unroll
            for (int off = 8; off >= 1; off >>= 1)
                rs += __shfl_xor_sync(0xffffffffu, rs, off);
            lrow[i] = lrow[i] * corr + rs;
            mrow[i] = mn;
#pragma unroll
            for (int j = 0; j < 4; j++) O[i][j] *= corr;
        }
        __syncthreads();   // everyone done reading Ks

        // write P into Ks buffer
#pragma unroll
        for (int i = 0; i < 4; i++)
#pragma unroll
            for (int j = 0; j < 4; j++)
                Ks[(ty + 16 * i) * ST + tx + 16 * j] = s4[i][j];
        __syncthreads();

        // O += P @ V
#pragma unroll 8
        for (int c = 0; c < 64; c++) {
            float pr[4], vr[4];
#pragma unroll
            for (int i = 0; i < 4; i++) pr[i] = Ks[(ty + 16 * i) * ST + c];
#pragma unroll
            for (int j = 0; j < 4; j++) vr[j] = Vs[c * ST + tx + 16 * j];
#pragma unroll
            for (int i = 0; i < 4; i++)
#pragma unroll
                for (int j = 0; j < 4; j++) O[i][j] += pr[i] * vr[j];
        }
        __syncthreads();
    }

    // epilogue: normalize and store to X[b][l][h*64+d]
    const int b = bh >> 4, h = bh & 15;
#pragma unroll
    for (int i = 0; i < 4; i++) {
        float inv = 1.f / lrow[i];
        int row = qt * 64 + ty + 16 * i;
#pragma unroll
        for (int j = 0; j < 4; j++) {
            X[((size_t)b * LSEQ + row) * NF + h * DK + tx + 16 * j] = O[i][j] * inv;
        }
    }
}

// ---------------------------------------------------------------------------
extern "C" void kernel_launch(void* const* d_in, const int* in_sizes, int n_in,
                              void* d_out, int out_size)
{
    const float* query = (const float*)d_in[0];
    const float* key   = (const float*)d_in[1];
    const float* value = (const float*)d_in[2];
    const float* Wq    = (const float*)d_in[3];
    const float* bq    = (const float*)d_in[4];
    const float* Wk    = (const float*)d_in[5];
    const float* bk    = (const float*)d_in[6];
    const float* Wv    = (const float*)d_in[7];
    const float* bv    = (const float*)d_in[8];
    const float* Wo    = (const float*)d_in[9];
    const float* bo    = (const float*)d_in[10];
    float* out = (float*)d_out;

    float *qp, *kp, *vp, *xp;
    cudaGetSymbolAddress((void**)&qp, g_q);
    cudaGetSymbolAddress((void**)&kp, g_k);
    cudaGetSymbolAddress((void**)&vp, g_v);
    cudaGetSymbolAddress((void**)&xp, g_x);

    const int attn_smem = 3 * 64 * ST * (int)sizeof(float);   // 50688
    cudaFuncSetAttribute(attn_kernel,
                         cudaFuncAttributeMaxDynamicSharedMemorySize, attn_smem);

    dim3 gemm_grid(NF / 128, MTOT / 128);   // (8, 64)

    gemm_bias_kernel<<<gemm_grid, 256>>>(query, Wq, bq, qp, 1);
    gemm_bias_kernel<<<gemm_grid, 256>>>(key,   Wk, bk, kp, 1);
    gemm_bias_kernel<<<gemm_grid, 256>>>(value, Wv, bv, vp, 1);

    dim3 attn_grid(LSEQ / 64, BATCH * NHEAD);   // (32, 64)
    attn_kernel<<<attn_grid, 256, attn_smem>>>(qp, kp, vp, xp);

    gemm_bias_kernel<<<gemm_grid, 256>>>(xp, Wo, bo, out, 0);
}

// round 2
// speedup vs baseline: 1.0727x; 1.0727x over previous
#include <cuda_runtime.h>
#include <math.h>

#define BATCH 4
#define LSEQ  2048
#define NHEAD 16
#define DK    64
#define NF    1024
#define MTOT  (BATCH * LSEQ)   // 8192

// Scratch (device globals: no allocations allowed in kernel_launch)
__device__ float g_q[(size_t)BATCH * NHEAD * LSEQ * DK];
__device__ float g_k[(size_t)BATCH * NHEAD * LSEQ * DK];
__device__ float g_v[(size_t)BATCH * NHEAD * LSEQ * DK];
__device__ float g_x[(size_t)MTOT * NF];

// ---------------------------------------------------------------------------
// SGEMM: C[M=8192, N=1024] = A[8192,1024] @ W[1024,1024] + bias
// mode 0: C row-major [m][n]
// mode 1: scatter to [b*16+h][l][d] layout (b=m>>11, l=m&2047, h=n>>6, d=n&63)
// 128x128x16 tile, 256 threads, 8x8 per-thread register tile with CONTIGUOUS
// 4-wide subtiles -> all smem reads are LDS.128.
// ---------------------------------------------------------------------------
__global__ __launch_bounds__(256) void gemm_bias_kernel(
    const float* __restrict__ A, const float* __restrict__ W,
    const float* __restrict__ bias, float* __restrict__ C, int mode)
{
    __shared__ __align__(16) float As[16][132];   // As[k][row], 528B row stride
    __shared__ __align__(16) float Ws[16][132];   // Ws[k][n]

    const int tid = threadIdx.x;
    const int tx = tid & 15;
    const int ty = tid >> 4;
    const int m0 = blockIdx.y * 128;
    const int n0 = blockIdx.x * 128;

    const float4* A4 = (const float4*)A;
    const float4* W4 = (const float4*)W;

    float acc[8][8];
#pragma unroll
    for (int i = 0; i < 8; i++)
#pragma unroll
        for (int j = 0; j < 8; j++) acc[i][j] = 0.f;

    float4 pa[2], pw[2];
    // prefetch kt = 0
#pragma unroll
    for (int s = 0; s < 2; s++) {
        int idx = tid + 256 * s;
        int ar = idx >> 2, kc = idx & 3;
        pa[s] = A4[(size_t)(m0 + ar) * (NF / 4) + kc];
        int wr = idx >> 5, nc = idx & 31;
        pw[s] = W4[(size_t)wr * (NF / 4) + (n0 >> 2) + nc];
    }

    const int NKT = NF / 16;   // 64
    for (int kt = 0; kt < NKT; kt++) {
#pragma unroll
        for (int s = 0; s < 2; s++) {
            int idx = tid + 256 * s;
            int ar = idx >> 2, kc = idx & 3;
            As[kc * 4 + 0][ar] = pa[s].x;
            As[kc * 4 + 1][ar] = pa[s].y;
            As[kc * 4 + 2][ar] = pa[s].z;
            As[kc * 4 + 3][ar] = pa[s].w;
            int wr = idx >> 5, nc = idx & 31;
            ((float4*)(&Ws[wr][0]))[nc] = pw[s];
        }
        __syncthreads();

        if (kt + 1 < NKT) {
#pragma unroll
            for (int s = 0; s < 2; s++) {
                int idx = tid + 256 * s;
                int ar = idx >> 2, kc = idx & 3;
                pa[s] = A4[(size_t)(m0 + ar) * (NF / 4) + (kt + 1) * 4 + kc];
                int wr = idx >> 5, nc = idx & 31;
                pw[s] = W4[(size_t)((kt + 1) * 16 + wr) * (NF / 4) + (n0 >> 2) + nc];
            }
        }

#pragma unroll
        for (int k = 0; k < 16; k++) {
            float4 a0 = *(const float4*)&As[k][4 * ty];
            float4 a1 = *(const float4*)&As[k][64 + 4 * ty];
            float4 b0 = *(const float4*)&Ws[k][4 * tx];
            float4 b1 = *(const float4*)&Ws[k][64 + 4 * tx];
            float ra[8] = {a0.x, a0.y, a0.z, a0.w, a1.x, a1.y, a1.z, a1.w};
            float rb[8] = {b0.x, b0.y, b0.z, b0.w, b1.x, b1.y, b1.z, b1.w};
#pragma unroll
            for (int i = 0; i < 8; i++)
#pragma unroll
                for (int j = 0; j < 8; j++) acc[i][j] += ra[i] * rb[j];
        }
        __syncthreads();
    }

    // epilogue: rows m0 + ib*64 + 4ty+ii, cols n0 + jb*64 + 4tx+jj (float4)
#pragma unroll
    for (int ib = 0; ib < 2; ib++) {
#pragma unroll
        for (int ii = 0; ii < 4; ii++) {
            int m = m0 + ib * 64 + 4 * ty + ii;
#pragma unroll
            for (int jb = 0; jb < 2; jb++) {
                int n = n0 + jb * 64 + 4 * tx;
                float4 v;
                v.x = acc[ib * 4 + ii][jb * 4 + 0] + bias[n + 0];
                v.y = acc[ib * 4 + ii][jb * 4 + 1] + bias[n + 1];
                v.z = acc[ib * 4 + ii][jb * 4 + 2] + bias[n + 2];
                v.w = acc[ib * 4 + ii][jb * 4 + 3] + bias[n + 3];
                if (mode == 0) {
                    *(float4*)&C[(size_t)m * NF + n] = v;
                } else {
                    int b = m >> 11, l = m & 2047;
                    int h = n >> 6,  d = n & 63;
                    *(float4*)&C[(((size_t)(b * NHEAD + h)) * LSEQ + l) * DK + d] = v;
                }
            }
        }
    }
}

// ---------------------------------------------------------------------------
// Flash attention, fp32, swizzled smem -> all inner-loop reads are LDS.128.
// One block = one (b,h) x 64-query tile. 256 threads, 4x4 contiguous tile:
// rows 4ty+i, cols 4tx+j. Swizzle: float index = r*64 + ((g^(r>>2))&15)*4 + k%4
// where g = k/4. Zero padding; 16B aligned float4 access; <=2-way conflicts.
// V stored transposed (Vt[d][c]) so the PV phase vectorizes over c.
// ---------------------------------------------------------------------------
__device__ __forceinline__ int swz(int r, int k) {
    return r * 64 + ((((k >> 2) ^ (r >> 2)) & 15) << 2) + (k & 3);
}

__global__ __launch_bounds__(256) void attn_kernel(
    const float* __restrict__ Q, const float* __restrict__ K,
    const float* __restrict__ V, float* __restrict__ X)
{
    extern __shared__ float sm[];
    float* Qs = sm;             // [64*64] swizzled [row][k]
    float* Ks = sm + 4096;      // [64*64] swizzled [row][k]; reused for P[r][c]
    float* Vt = sm + 8192;      // [64*64] swizzled TRANSPOSED [d][c]

    const int tid = threadIdx.x;
    const int tx = tid & 15;
    const int ty = tid >> 4;
    const int qt = blockIdx.x;      // query tile 0..31
    const int bh = blockIdx.y;      // 0..63

    const float* Qg = Q + ((size_t)bh * LSEQ + qt * 64) * DK;
    const float* Kg = K + (size_t)bh * LSEQ * DK;
    const float* Vg = V + (size_t)bh * LSEQ * DK;

    // load Q tile (64x64 floats) as float2, coalesced; store swizzled
    {
        const float2* Qg2 = (const float2*)Qg;
#pragma unroll
        for (int s = 0; s < 8; s++) {
            int idx = tid + 256 * s;
            int r = idx >> 5, c2 = idx & 31;
            float2 v = Qg2[r * 32 + c2];
            *(float2*)&Qs[swz(r, 2 * c2)] = v;   // same granule, contiguous
        }
    }

    float mrow[4], lrow[4], O[4][4];
#pragma unroll
    for (int i = 0; i < 4; i++) {
        mrow[i] = -1e30f;
        lrow[i] = 0.f;
#pragma unroll
        for (int j = 0; j < 4; j++) O[i][j] = 0.f;
    }

    const float scale = 0.125f;   // 1/sqrt(64)

    for (int kt = 0; kt < LSEQ / 64; kt++) {
        const float2* Kg2 = (const float2*)(Kg + (size_t)kt * 64 * DK);
        const float2* Vg2 = (const float2*)(Vg + (size_t)kt * 64 * DK);
#pragma unroll
        for (int s = 0; s < 8; s++) {
            int idx = tid + 256 * s;
            int r = idx >> 5, c2 = idx & 31;
            float2 kv = Kg2[r * 32 + c2];
            *(float2*)&Ks[swz(r, 2 * c2)] = kv;
            float2 vv = Vg2[r * 32 + c2];
            Vt[swz(2 * c2, r)]     = vv.x;       // transpose on store
            Vt[swz(2 * c2 + 1, r)] = vv.y;
        }
        __syncthreads();

        // S = Q K^T : vectorized over k (4 at a time, all LDS.128)
        float s4[4][4];
#pragma unroll
        for (int i = 0; i < 4; i++)
#pragma unroll
            for (int j = 0; j < 4; j++) s4[i][j] = 0.f;

#pragma unroll 4
        for (int k0 = 0; k0 < DK; k0 += 4) {
            float4 qa[4], kb[4];
#pragma unroll
            for (int i = 0; i < 4; i++) qa[i] = *(const float4*)&Qs[swz(4 * ty + i, k0)];
#pragma unroll
            for (int j = 0; j < 4; j++) kb[j] = *(const float4*)&Ks[swz(4 * tx + j, k0)];
#pragma unroll
            for (int i = 0; i < 4; i++)
#pragma unroll
                for (int j = 0; j < 4; j++) {
                    s4[i][j] += qa[i].x * kb[j].x;
                    s4[i][j] += qa[i].y * kb[j].y;
                    s4[i][j] += qa[i].z * kb[j].z;
                    s4[i][j] += qa[i].w * kb[j].w;
                }
        }

        // online softmax per row (reduce across 16 tx lanes)
#pragma unroll
        for (int i = 0; i < 4; i++) {
            float tmax = -1e30f;
#pragma unroll
            for (int j = 0; j < 4; j++) {
                s4[i][j] *= scale;
                tmax = fmaxf(tmax, s4[i][j]);
            }
#pragma unroll
            for (int off = 8; off >= 1; off >>= 1)
                tmax = fmaxf(tmax, __shfl_xor_sync(0xffffffffu, tmax, off));
            float mn = fmaxf(mrow[i], tmax);
            float corr = __expf(mrow[i] - mn);
            float rs = 0.f;
#pragma unroll
            for (int j = 0; j < 4; j++) {
                float p = __expf(s4[i][j] - mn);
                s4[i][j] = p;
                rs += p;
            }
#pragma unroll
            for (int off = 8; off >= 1; off >>= 1)
                rs += __shfl_xor_sync(0xffffffffu, rs, off);
            lrow[i] = lrow[i] * corr + rs;
            mrow[i] = mn;
#pragma unroll
            for (int j = 0; j < 4; j++) O[i][j] *= corr;
        }
        __syncthreads();   // everyone done reading Ks

        // write P into Ks buffer: one STS.128 per row (cols 4tx..4tx+3 share granule)
#pragma unroll
        for (int i = 0; i < 4; i++) {
            float4 p = make_float4(s4[i][0], s4[i][1], s4[i][2], s4[i][3]);
            *(float4*)&Ks[swz(4 * ty + i, 4 * tx)] = p;
        }
        __syncthreads();

        // O += P @ V : vectorized over c (4 at a time, all LDS.128)
#pragma unroll 4
        for (int c0 = 0; c0 < 64; c0 += 4) {
            float4 pr[4], vr[4];
#pragma unroll
            for (int i = 0; i < 4; i++) pr[i] = *(const float4*)&Ks[swz(4 * ty + i, c0)];
#pragma unroll
            for (int j = 0; j < 4; j++) vr[j] = *(const float4*)&Vt[swz(4 * tx + j, c0)];
#pragma unroll
            for (int i = 0; i < 4; i++)
#pragma unroll
                for (int j = 0; j < 4; j++) {
                    O[i][j] += pr[i].x * vr[j].x;
                    O[i][j] += pr[i].y * vr[j].y;
                    O[i][j] += pr[i].z * vr[j].z;
                    O[i][j] += pr[i].w * vr[j].w;
                }
        }
        __syncthreads();
    }

    // epilogue: normalize and store to X[b][l][h*64+d], float4 stores
    const int b = bh >> 4, h = bh & 15;
#pragma unroll
    for (int i = 0; i < 4; i++) {
        float inv = 1.f / lrow[i];
        int row = qt * 64 + 4 * ty + i;
        float4 v = make_float4(O[i][0] * inv, O[i][1] * inv,
                               O[i][2] * inv, O[i][3] * inv);
        *(float4*)&X[((size_t)b * LSEQ + row) * NF + h * DK + 4 * tx] = v;
    }
}

// ---------------------------------------------------------------------------
extern "C" void kernel_launch(void* const* d_in, const int* in_sizes, int n_in,
                              void* d_out, int out_size)
{
    const float* query = (const float*)d_in[0];
    const float* key   = (const float*)d_in[1];
    const float* value = (const float*)d_in[2];
    const float* Wq    = (const float*)d_in[3];
    const float* bq    = (const float*)d_in[4];
    const float* Wk    = (const float*)d_in[5];
    const float* bk    = (const float*)d_in[6];
    const float* Wv    = (const float*)d_in[7];
    const float* bv    = (const float*)d_in[8];
    const float* Wo    = (const float*)d_in[9];
    const float* bo    = (const float*)d_in[10];
    float* out = (float*)d_out;

    float *qp, *kp, *vp, *xp;
    cudaGetSymbolAddress((void**)&qp, g_q);
    cudaGetSymbolAddress((void**)&kp, g_k);
    cudaGetSymbolAddress((void**)&vp, g_v);
    cudaGetSymbolAddress((void**)&xp, g_x);

    const int attn_smem = 3 * 4096 * (int)sizeof(float);   // 49152
    cudaFuncSetAttribute(attn_kernel,
                         cudaFuncAttributeMaxDynamicSharedMemorySize, attn_smem);

    dim3 gemm_grid(NF / 128, MTOT / 128);   // (8, 64)

    gemm_bias_kernel<<<gemm_grid, 256>>>(query, Wq, bq, qp, 1);
    gemm_bias_kernel<<<gemm_grid, 256>>>(key,   Wk, bk, kp, 1);
    gemm_bias_kernel<<<gemm_grid, 256>>>(value, Wv, bv, vp, 1);

    dim3 attn_grid(LSEQ / 64, BATCH * NHEAD);   // (32, 64)
    attn_kernel<<<attn_grid, 256, attn_smem>>>(qp, kp, vp, xp);

    gemm_bias_kernel<<<gemm_grid, 256>>>(xp, Wo, bo, out, 0);
}

// round 4
// speedup vs baseline: 1.3241x; 1.2343x over previous
#include <cuda_runtime.h>
#include <cuda_bf16.h>
#include <cstdint>
#include <math.h>

#define BATCH 4
#define LSEQ  2048
#define NHEAD 16
#define DK    64
#define NF    1024
#define MTOT  (BATCH * LSEQ)   // 8192

// ---------------------------------------------------------------------------
// Scratch (device globals: no allocations allowed)
// ---------------------------------------------------------------------------
__device__ float g_q[(size_t)BATCH * NHEAD * LSEQ * DK];
__device__ float g_k[(size_t)BATCH * NHEAD * LSEQ * DK];
__device__ float g_v[(size_t)BATCH * NHEAD * LSEQ * DK];
__device__ float g_x[(size_t)MTOT * NF];
__device__ __nv_bfloat16 g_ah[(size_t)MTOT * NF];   // activation hi
__device__ __nv_bfloat16 g_al[(size_t)MTOT * NF];   // activation lo
__device__ __nv_bfloat16 g_wh[(size_t)NF * NF];     // weight hi, transposed [N][K]
__device__ __nv_bfloat16 g_wl[(size_t)NF * NF];     // weight lo, transposed [N][K]

// ---------------------------------------------------------------------------
// Warp-MMA helpers (base PTX features, legal at compute_103)
// ---------------------------------------------------------------------------
__device__ __forceinline__ uint32_t smem_u32(const void* p) {
    uint32_t a;
    asm("{ .reg .u64 t; cvta.to.shared.u64 t, %1; cvt.u32.u64 %0, t; }"
        : "=r"(a) : "l"(p));
    return a;
}
__device__ __forceinline__ void ldsm_x4(uint32_t addr, uint32_t& r0, uint32_t& r1,
                                        uint32_t& r2, uint32_t& r3) {
    asm volatile("ldmatrix.sync.aligned.m8n8.x4.shared.b16 {%0,%1,%2,%3}, [%4];"
                 : "=r"(r0), "=r"(r1), "=r"(r2), "=r"(r3) : "r"(addr));
}
__device__ __forceinline__ void mma16816(float* c, const uint32_t* a, const uint32_t* b) {
    asm volatile(
        "mma.sync.aligned.m16n8k16.row.col.f32.bf16.bf16.f32 "
        "{%0,%1,%2,%3}, {%4,%5,%6,%7}, {%8,%9}, {%0,%1,%2,%3};"
        : "+f"(c[0]), "+f"(c[1]), "+f"(c[2]), "+f"(c[3])
        : "r"(a[0]), "r"(a[1]), "r"(a[2]), "r"(a[3]), "r"(b[0]), "r"(b[1]));
}

// ---------------------------------------------------------------------------
// Split fp32 -> (hi, lo) bf16
// ---------------------------------------------------------------------------
__global__ __launch_bounds__(256) void split_act(
    const float* __restrict__ x, __nv_bfloat162* __restrict__ h2,
    __nv_bfloat162* __restrict__ l2, int n4)
{
    int i = blockIdx.x * blockDim.x + threadIdx.x;
    if (i >= n4) return;
    float4 v = ((const float4*)x)[i];
    __nv_bfloat16 ha = __float2bfloat16(v.x);
    __nv_bfloat16 hb = __float2bfloat16(v.y);
    __nv_bfloat16 hc = __float2bfloat16(v.z);
    __nv_bfloat16 hd = __float2bfloat16(v.w);
    __nv_bfloat16 la = __float2bfloat16(v.x - __bfloat162float(ha));
    __nv_bfloat16 lb = __float2bfloat16(v.y - __bfloat162float(hb));
    __nv_bfloat16 lc = __float2bfloat16(v.z - __bfloat162float(hc));
    __nv_bfloat16 ld = __float2bfloat16(v.w - __bfloat162float(hd));
    __nv_bfloat162 p;
    p.x = ha; p.y = hb; h2[2 * i] = p;
    p.x = hc; p.y = hd; h2[2 * i + 1] = p;
    p.x = la; p.y = lb; l2[2 * i] = p;
    p.x = lc; p.y = ld; l2[2 * i + 1] = p;
}

// Split + transpose weights: W[K][N] fp32 -> Wt_h[N][K], Wt_l[N][K] bf16
__global__ __launch_bounds__(256) void split_wT(
    const float* __restrict__ W, __nv_bfloat16* __restrict__ th,
    __nv_bfloat16* __restrict__ tl)
{
    __shared__ float t[32][33];
    int tx = threadIdx.x, ty = threadIdx.y;   // 32 x 8
    int bx = blockIdx.x, by = blockIdx.y;
#pragma unroll
    for (int i = 0; i < 32; i += 8)
        t[ty + i][tx] = W[(size_t)(by * 32 + ty + i) * NF + bx * 32 + tx];
    __syncthreads();
#pragma unroll
    for (int i = 0; i < 32; i += 8) {
        float v = t[tx][ty + i];
        __nv_bfloat16 h = __float2bfloat16(v);
        __nv_bfloat16 l = __float2bfloat16(v - __bfloat162float(h));
        size_t o = (size_t)(bx * 32 + ty + i) * NF + by * 32 + tx;
        th[o] = h; tl[o] = l;
    }
}

// ---------------------------------------------------------------------------
// HMMA GEMM: C[8192,1024] = A @ W + bias via split-bf16 3-term emulation.
// CTA tile 128x128, 8 warps (warp tile 32x64), K chunks of 64.
// smem: Ah/Al [128 rows][64 k] bf16, Bh/Bl (=W^T) [128 n][64 k] bf16,
// 128B rows with XOR-granule swizzle -> ldmatrix conflict-free.
// mode 0: row-major out; mode 1: scatter to [b*16+h][l][d].
// ---------------------------------------------------------------------------
#define SM_AH 0
#define SM_AL 16384
#define SM_BH 32768
#define SM_BL 49152
#define GEMM_SMEM 65536

__global__ __launch_bounds__(256) void gemm_mma(
    const __nv_bfloat16* __restrict__ Ah, const __nv_bfloat16* __restrict__ Al,
    const __nv_bfloat16* __restrict__ Bh, const __nv_bfloat16* __restrict__ Bl,
    const float* __restrict__ bias, float* __restrict__ C, int mode)
{
    extern __shared__ char smem[];
    const uint32_t sbase = smem_u32(smem);

    const int tid = threadIdx.x;
    const int lane = tid & 31;
    const int wid = tid >> 5;
    const int wy = wid & 3;        // m subtile (4 x 32 rows)
    const int wx = wid >> 2;       // n subtile (2 x 64 cols)
    const int m0 = blockIdx.y * 128;
    const int n0 = blockIdx.x * 128;

    const uint4* Ah4 = (const uint4*)Ah;
    const uint4* Al4 = (const uint4*)Al;
    const uint4* Bh4 = (const uint4*)Bh;
    const uint4* Bl4 = (const uint4*)Bl;

    float acc[2][8][4];
#pragma unroll
    for (int mt = 0; mt < 2; mt++)
#pragma unroll
        for (int nt = 0; nt < 8; nt++)
#pragma unroll
            for (int q = 0; q < 4; q++) acc[mt][nt][q] = 0.f;

    // ldmatrix row/granule for this lane (row index within a 16-row tile)
    const int lrow = lane & 15;
    const int lkh  = lane >> 4;    // 0/1: k-halves

    for (int kc = 0; kc < NF / 64; kc++) {
        // Load 4 tiles of 128x64 bf16 (each 8KB), swizzled: granule g' = g ^ (r&7)
#pragma unroll
        for (int it = 0; it < 4; it++) {
            int idx = tid + 256 * it;
            int r = idx >> 3, g = idx & 7;
            uint32_t so = (uint32_t)(r * 128 + ((g ^ (r & 7)) * 16));
            size_t goA = (size_t)(m0 + r) * (NF / 8) + kc * 8 + g;
            size_t goB = (size_t)(n0 + r) * (NF / 8) + kc * 8 + g;
            *(uint4*)(smem + SM_AH + so) = Ah4[goA];
            *(uint4*)(smem + SM_AL + so) = Al4[goA];
            *(uint4*)(smem + SM_BH + so) = Bh4[goB];
            *(uint4*)(smem + SM_BL + so) = Bl4[goB];
        }
        __syncthreads();

#pragma unroll
        for (int ks = 0; ks < 4; ks++) {
            const int gg = ks * 2 + lkh;
            // A fragments (hi & lo) for both 16-row tiles
            uint32_t ahf[2][4], alf[2][4];
#pragma unroll
            for (int mt = 0; mt < 2; mt++) {
                int row = wy * 32 + mt * 16 + lrow;
                uint32_t off = (uint32_t)(row * 128 + ((gg ^ (row & 7)) * 16));
                ldsm_x4(sbase + SM_AH + off, ahf[mt][0], ahf[mt][1], ahf[mt][2], ahf[mt][3]);
                ldsm_x4(sbase + SM_AL + off, alf[mt][0], alf[mt][1], alf[mt][2], alf[mt][3]);
            }
            // B fragment pairs: 4 x (16 n-rows) covering 8 n-tiles
#pragma unroll
            for (int btp = 0; btp < 4; btp++) {
                int row = wx * 64 + btp * 16 + lrow;
                uint32_t off = (uint32_t)(row * 128 + ((gg ^ (row & 7)) * 16));
                uint32_t h0, h1, h2, h3, l0, l1, l2, l3;
                ldsm_x4(sbase + SM_BH + off, h0, h1, h2, h3);
                ldsm_x4(sbase + SM_BL + off, l0, l1, l2, l3);
                uint32_t bfh[2][2] = {{h0, h2}, {h1, h3}};   // n-even, n-odd
                uint32_t bfl[2][2] = {{l0, l2}, {l1, l3}};
#pragma unroll
                for (int mt = 0; mt < 2; mt++)
#pragma unroll
                    for (int nn = 0; nn < 2; nn++) {
                        float* c = acc[mt][btp * 2 + nn];
                        mma16816(c, ahf[mt], bfh[nn]);   // Ah*Bh
                        mma16816(c, ahf[mt], bfl[nn]);   // Ah*Bl
                        mma16816(c, alf[mt], bfh[nn]);   // Al*Bh
                    }
            }
        }
        __syncthreads();
    }

    // Epilogue: c0,c1 -> (row, col..col+1); c2,c3 -> (row+8, same cols)
#pragma unroll
    for (int mt = 0; mt < 2; mt++) {
        int mrow = m0 + wy * 32 + mt * 16 + (lane >> 2);
#pragma unroll
        for (int nt = 0; nt < 8; nt++) {
            int n = n0 + wx * 64 + nt * 8 + (lane & 3) * 2;
            float2 bv = *(const float2*)&bias[n];
            float2 v0, v1;
            v0.x = acc[mt][nt][0] + bv.x;
            v0.y = acc[mt][nt][1] + bv.y;
            v1.x = acc[mt][nt][2] + bv.x;
            v1.y = acc[mt][nt][3] + bv.y;
            if (mode == 0) {
                *(float2*)&C[(size_t)mrow * NF + n] = v0;
                *(float2*)&C[(size_t)(mrow + 8) * NF + n] = v1;
            } else {
                int h = n >> 6, d = n & 63;
                int b = mrow >> 11, l = mrow & 2047;
                *(float2*)&C[(((size_t)(b * NHEAD + h)) * LSEQ + l) * DK + d] = v0;
                int b2 = (mrow + 8) >> 11, l2v = (mrow + 8) & 2047;
                *(float2*)&C[(((size_t)(b2 * NHEAD + h)) * LSEQ + l2v) * DK + d] = v1;
            }
        }
    }
}

// ---------------------------------------------------------------------------
// Flash attention, fp32 (unchanged; known good)
// ---------------------------------------------------------------------------
__device__ __forceinline__ int swz(int r, int k) {
    return r * 64 + ((((k >> 2) ^ (r >> 2)) & 15) << 2) + (k & 3);
}

__global__ __launch_bounds__(256) void attn_kernel(
    const float* __restrict__ Q, const float* __restrict__ K,
    const float* __restrict__ V, float* __restrict__ X)
{
    extern __shared__ float sm[];
    float* Qs = sm;
    float* Ks = sm + 4096;
    float* Vt = sm + 8192;

    const int tid = threadIdx.x;
    const int tx = tid & 15;
    const int ty = tid >> 4;
    const int qt = blockIdx.x;
    const int bh = blockIdx.y;

    const float* Qg = Q + ((size_t)bh * LSEQ + qt * 64) * DK;
    const float* Kg = K + (size_t)bh * LSEQ * DK;
    const float* Vg = V + (size_t)bh * LSEQ * DK;

    {
        const float2* Qg2 = (const float2*)Qg;
#pragma unroll
        for (int s = 0; s < 8; s++) {
            int idx = tid + 256 * s;
            int r = idx >> 5, c2 = idx & 31;
            float2 v = Qg2[r * 32 + c2];
            *(float2*)&Qs[swz(r, 2 * c2)] = v;
        }
    }

    float mrow[4], lrow[4], O[4][4];
#pragma unroll
    for (int i = 0; i < 4; i++) {
        mrow[i] = -1e30f;
        lrow[i] = 0.f;
#pragma unroll
        for (int j = 0; j < 4; j++) O[i][j] = 0.f;
    }

    const float scale = 0.125f;

    for (int kt = 0; kt < LSEQ / 64; kt++) {
        const float2* Kg2 = (const float2*)(Kg + (size_t)kt * 64 * DK);
        const float2* Vg2 = (const float2*)(Vg + (size_t)kt * 64 * DK);
#pragma unroll
        for (int s = 0; s < 8; s++) {
            int idx = tid + 256 * s;
            int r = idx >> 5, c2 = idx & 31;
            float2 kv = Kg2[r * 32 + c2];
            *(float2*)&Ks[swz(r, 2 * c2)] = kv;
            float2 vv = Vg2[r * 32 + c2];
            Vt[swz(2 * c2, r)]     = vv.x;
            Vt[swz(2 * c2 + 1, r)] = vv.y;
        }
        __syncthreads();

        float s4[4][4];
#pragma unroll
        for (int i = 0; i < 4; i++)
#pragma unroll
            for (int j = 0; j < 4; j++) s4[i][j] = 0.f;

#pragma unroll 4
        for (int k0 = 0; k0 < DK; k0 += 4) {
            float4 qa[4], kb[4];
#pragma unroll
            for (int i = 0; i < 4; i++) qa[i] = *(const float4*)&Qs[swz(4 * ty + i, k0)];
#pragma unroll
            for (int j = 0; j < 4; j++) kb[j] = *(const float4*)&Ks[swz(4 * tx + j, k0)];
#pragma unroll
            for (int i = 0; i < 4; i++)
#pragma unroll
                for (int j = 0; j < 4; j++) {
                    s4[i][j] += qa[i].x * kb[j].x;
                    s4[i][j] += qa[i].y * kb[j].y;
                    s4[i][j] += qa[i].z * kb[j].z;
                    s4[i][j] += qa[i].w * kb[j].w;
                }
        }

#pragma unroll
        for (int i = 0; i < 4; i++) {
            float tmax = -1e30f;
#pragma unroll
            for (int j = 0; j < 4; j++) {
                s4[i][j] *= scale;
                tmax = fmaxf(tmax, s4[i][j]);
            }
#pragma unroll
            for (int off = 8; off >= 1; off >>= 1)
                tmax = fmaxf(tmax, __shfl_xor_sync(0xffffffffu, tmax, off));
            float mn = fmaxf(mrow[i], tmax);
            float corr = __expf(mrow[i] - mn);
            float rs = 0.f;
#pragma unroll
            for (int j = 0; j < 4; j++) {
                float p = __expf(s4[i][j] - mn);
                s4[i][j] = p;
                rs += p;
            }
#pragma unroll
            for (int off = 8; off >= 1; off >>= 1)
                rs += __shfl_xor_sync(0xffffffffu, rs, off);
            lrow[i] = lrow[i] * corr + rs;
            mrow[i] = mn;
#pragma unroll
            for (int j = 0; j < 4; j++) O[i][j] *= corr;
        }
        __syncthreads();

#pragma unroll
        for (int i = 0; i < 4; i++) {
            float4 p = make_float4(s4[i][0], s4[i][1], s4[i][2], s4[i][3]);
            *(float4*)&Ks[swz(4 * ty + i, 4 * tx)] = p;
        }
        __syncthreads();

#pragma unroll 4
        for (int c0 = 0; c0 < 64; c0 += 4) {
            float4 pr[4], vr[4];
#pragma unroll
            for (int i = 0; i < 4; i++) pr[i] = *(const float4*)&Ks[swz(4 * ty + i, c0)];
#pragma unroll
            for (int j = 0; j < 4; j++) vr[j] = *(const float4*)&Vt[swz(4 * tx + j, c0)];
#pragma unroll
            for (int i = 0; i < 4; i++)
#pragma unroll
                for (int j = 0; j < 4; j++) {
                    O[i][j] += pr[i].x * vr[j].x;
                    O[i][j] += pr[i].y * vr[j].y;
                    O[i][j] += pr[i].z * vr[j].z;
                    O[i][j] += pr[i].w * vr[j].w;
                }
        }
        __syncthreads();
    }

    const int b = bh >> 4, h = bh & 15;
#pragma unroll
    for (int i = 0; i < 4; i++) {
        float inv = 1.f / lrow[i];
        int row = qt * 64 + 4 * ty + i;
        float4 v = make_float4(O[i][0] * inv, O[i][1] * inv,
                               O[i][2] * inv, O[i][3] * inv);
        *(float4*)&X[((size_t)b * LSEQ + row) * NF + h * DK + 4 * tx] = v;
    }
}

// ---------------------------------------------------------------------------
extern "C" void kernel_launch(void* const* d_in, const int* in_sizes, int n_in,
                              void* d_out, int out_size)
{
    const float* query = (const float*)d_in[0];
    const float* key   = (const float*)d_in[1];
    const float* value = (const float*)d_in[2];
    const float* Wq    = (const float*)d_in[3];
    const float* bq    = (const float*)d_in[4];
    const float* Wk    = (const float*)d_in[5];
    const float* bk    = (const float*)d_in[6];
    const float* Wv    = (const float*)d_in[7];
    const float* bv    = (const float*)d_in[8];
    const float* Wo    = (const float*)d_in[9];
    const float* bo    = (const float*)d_in[10];
    float* out = (float*)d_out;

    float *qp, *kp, *vp, *xp;
    __nv_bfloat16 *ah, *al, *wh, *wl;
    cudaGetSymbolAddress((void**)&qp, g_q);
    cudaGetSymbolAddress((void**)&kp, g_k);
    cudaGetSymbolAddress((void**)&vp, g_v);
    cudaGetSymbolAddress((void**)&xp, g_x);
    cudaGetSymbolAddress((void**)&ah, g_ah);
    cudaGetSymbolAddress((void**)&al, g_al);
    cudaGetSymbolAddress((void**)&wh, g_wh);
    cudaGetSymbolAddress((void**)&wl, g_wl);

    cudaFuncSetAttribute(gemm_mma,
                         cudaFuncAttributeMaxDynamicSharedMemorySize, GEMM_SMEM);
    const int attn_smem = 3 * 4096 * (int)sizeof(float);
    cudaFuncSetAttribute(attn_kernel,
                         cudaFuncAttributeMaxDynamicSharedMemorySize, attn_smem);

    const int n4 = MTOT * NF / 4;
    const int split_blocks = (n4 + 255) / 256;
    dim3 wt_grid(NF / 32, NF / 32), wt_block(32, 8);
    dim3 gemm_grid(NF / 128, MTOT / 128);      // (8, 64)

    // Q projection
    split_act<<<split_blocks, 256>>>(query, (__nv_bfloat162*)ah, (__nv_bfloat162*)al, n4);
    split_wT<<<wt_grid, wt_block>>>(Wq, wh, wl);
    gemm_mma<<<gemm_grid, 256, GEMM_SMEM>>>(ah, al, wh, wl, bq, qp, 1);
    // K projection
    split_act<<<split_blocks, 256>>>(key, (__nv_bfloat162*)ah, (__nv_bfloat162*)al, n4);
    split_wT<<<wt_grid, wt_block>>>(Wk, wh, wl);
    gemm_mma<<<gemm_grid, 256, GEMM_SMEM>>>(ah, al, wh, wl, bk, kp, 1);
    // V projection
    split_act<<<split_blocks, 256>>>(value, (__nv_bfloat162*)ah, (__nv_bfloat162*)al, n4);
    split_wT<<<wt_grid, wt_block>>>(Wv, wh, wl);
    gemm_mma<<<gemm_grid, 256, GEMM_SMEM>>>(ah, al, wh, wl, bv, vp, 1);

    // attention
    dim3 attn_grid(LSEQ / 64, BATCH * NHEAD);
    attn_kernel<<<attn_grid, 256, attn_smem>>>(qp, kp, vp, xp);

    // output projection
    split_act<<<split_blocks, 256>>>(xp, (__nv_bfloat162*)ah, (__nv_bfloat162*)al, n4);
    split_wT<<<wt_grid, wt_block>>>(Wo, wh, wl);
    gemm_mma<<<gemm_grid, 256, GEMM_SMEM>>>(ah, al, wh, wl, bo, out, 0);
}

// round 6
// speedup vs baseline: 2.6098x; 1.9710x over previous
#include <cuda_runtime.h>
#include <cuda_bf16.h>
#include <cstdint>
#include <math.h>

#define BATCH 4
#define LSEQ  2048
#define NHEAD 16
#define DK    64
#define NF    1024
#define MTOT  (BATCH * LSEQ)   // 8192

// ---------------------------------------------------------------------------
// Scratch (device globals)
// ---------------------------------------------------------------------------
__device__ __nv_bfloat16 g_qh[(size_t)BATCH * NHEAD * LSEQ * DK];
__device__ __nv_bfloat16 g_ql[(size_t)BATCH * NHEAD * LSEQ * DK];
__device__ __nv_bfloat16 g_kh[(size_t)BATCH * NHEAD * LSEQ * DK];
__device__ __nv_bfloat16 g_kl[(size_t)BATCH * NHEAD * LSEQ * DK];
__device__ __nv_bfloat16 g_vh[(size_t)BATCH * NHEAD * LSEQ * DK];
__device__ __nv_bfloat16 g_vl[(size_t)BATCH * NHEAD * LSEQ * DK];
__device__ __nv_bfloat16 g_ah[(size_t)MTOT * NF];   // activation hi
__device__ __nv_bfloat16 g_al[(size_t)MTOT * NF];   // activation lo
__device__ __nv_bfloat16 g_wh[(size_t)NF * NF];     // weight hi, transposed [N][K]
__device__ __nv_bfloat16 g_wl[(size_t)NF * NF];     // weight lo, transposed [N][K]

// ---------------------------------------------------------------------------
// Warp-MMA helpers (base PTX features, legal at compute_103)
// ---------------------------------------------------------------------------
__device__ __forceinline__ uint32_t smem_u32(const void* p) {
    uint32_t a;
    asm("{ .reg .u64 t; cvta.to.shared.u64 t, %1; cvt.u32.u64 %0, t; }"
        : "=r"(a) : "l"(p));
    return a;
}
__device__ __forceinline__ void ldsm_x4(uint32_t addr, uint32_t& r0, uint32_t& r1,
                                        uint32_t& r2, uint32_t& r3) {
    asm volatile("ldmatrix.sync.aligned.m8n8.x4.shared.b16 {%0,%1,%2,%3}, [%4];"
                 : "=r"(r0), "=r"(r1), "=r"(r2), "=r"(r3) : "r"(addr));
}
__device__ __forceinline__ void ldsm_x4_t(uint32_t addr, uint32_t& r0, uint32_t& r1,
                                          uint32_t& r2, uint32_t& r3) {
    asm volatile("ldmatrix.sync.aligned.m8n8.x4.trans.shared.b16 {%0,%1,%2,%3}, [%4];"
                 : "=r"(r0), "=r"(r1), "=r"(r2), "=r"(r3) : "r"(addr));
}
__device__ __forceinline__ void mma16816(float* c, const uint32_t* a, const uint32_t* b) {
    asm volatile(
        "mma.sync.aligned.m16n8k16.row.col.f32.bf16.bf16.f32 "
        "{%0,%1,%2,%3}, {%4,%5,%6,%7}, {%8,%9}, {%0,%1,%2,%3};"
        : "+f"(c[0]), "+f"(c[1]), "+f"(c[2]), "+f"(c[3])
        : "r"(a[0]), "r"(a[1]), "r"(a[2]), "r"(a[3]), "r"(b[0]), "r"(b[1]));
}
__device__ __forceinline__ void split2(float x, float y, uint32_t& h, uint32_t& l) {
    __nv_bfloat16 hx = __float2bfloat16(x), hy = __float2bfloat16(y);
    __nv_bfloat16 lx = __float2bfloat16(x - __bfloat162float(hx));
    __nv_bfloat16 ly = __float2bfloat16(y - __bfloat162float(hy));
    __nv_bfloat162 hh; hh.x = hx; hh.y = hy;
    __nv_bfloat162 ll; ll.x = lx; ll.y = ly;
    h = *reinterpret_cast<uint32_t*>(&hh);
    l = *reinterpret_cast<uint32_t*>(&ll);
}

// ---------------------------------------------------------------------------
// Split fp32 -> (hi, lo) bf16
// ---------------------------------------------------------------------------
__global__ __launch_bounds__(256) void split_act(
    const float* __restrict__ x, __nv_bfloat162* __restrict__ h2,
    __nv_bfloat162* __restrict__ l2, int n4)
{
    int i = blockIdx.x * blockDim.x + threadIdx.x;
    if (i >= n4) return;
    float4 v = ((const float4*)x)[i];
    uint32_t h0, l0, h1, l1;
    split2(v.x, v.y, h0, l0);
    split2(v.z, v.w, h1, l1);
    ((uint32_t*)h2)[2 * i] = h0; ((uint32_t*)h2)[2 * i + 1] = h1;
    ((uint32_t*)l2)[2 * i] = l0; ((uint32_t*)l2)[2 * i + 1] = l1;
}

// Split + transpose weights: W[K][N] fp32 -> Wt_h[N][K], Wt_l[N][K] bf16
__global__ __launch_bounds__(256) void split_wT(
    const float* __restrict__ W, __nv_bfloat16* __restrict__ th,
    __nv_bfloat16* __restrict__ tl)
{
    __shared__ float t[32][33];
    int tx = threadIdx.x, ty = threadIdx.y;   // 32 x 8
    int bx = blockIdx.x, by = blockIdx.y;
#pragma unroll
    for (int i = 0; i < 32; i += 8)
        t[ty + i][tx] = W[(size_t)(by * 32 + ty + i) * NF + bx * 32 + tx];
    __syncthreads();
#pragma unroll
    for (int i = 0; i < 32; i += 8) {
        float v = t[tx][ty + i];
        __nv_bfloat16 h = __float2bfloat16(v);
        __nv_bfloat16 l = __float2bfloat16(v - __bfloat162float(h));
        size_t o = (size_t)(bx * 32 + ty + i) * NF + by * 32 + tx;
        th[o] = h; tl[o] = l;
    }
}

// ---------------------------------------------------------------------------
// HMMA GEMM: C[8192,1024] = A @ W + bias via split-bf16 3-term emulation.
// mode 0: fp32 C row-major.
// mode 1: split result into bf16 hi/lo, scatter to [b*16+h][l][d] (Ch, Cl).
// ---------------------------------------------------------------------------
#define SM_AH 0
#define SM_AL 16384
#define SM_BH 32768
#define SM_BL 49152
#define GEMM_SMEM 65536

__global__ __launch_bounds__(256) void gemm_mma(
    const __nv_bfloat16* __restrict__ Ah, const __nv_bfloat16* __restrict__ Al,
    const __nv_bfloat16* __restrict__ Bh, const __nv_bfloat16* __restrict__ Bl,
    const float* __restrict__ bias, float* __restrict__ C,
    __nv_bfloat16* __restrict__ Ch, __nv_bfloat16* __restrict__ Cl, int mode)
{
    extern __shared__ char smem[];
    const uint32_t sbase = smem_u32(smem);

    const int tid = threadIdx.x;
    const int lane = tid & 31;
    const int wid = tid >> 5;
    const int wy = wid & 3;
    const int wx = wid >> 2;
    const int m0 = blockIdx.y * 128;
    const int n0 = blockIdx.x * 128;

    const uint4* Ah4 = (const uint4*)Ah;
    const uint4* Al4 = (const uint4*)Al;
    const uint4* Bh4 = (const uint4*)Bh;
    const uint4* Bl4 = (const uint4*)Bl;

    float acc[2][8][4];
#pragma unroll
    for (int mt = 0; mt < 2; mt++)
#pragma unroll
        for (int nt = 0; nt < 8; nt++)
#pragma unroll
            for (int q = 0; q < 4; q++) acc[mt][nt][q] = 0.f;

    const int lrow = lane & 15;
    const int lkh  = lane >> 4;

    for (int kc = 0; kc < NF / 64; kc++) {
#pragma unroll
        for (int it = 0; it < 4; it++) {
            int idx = tid + 256 * it;
            int r = idx >> 3, g = idx & 7;
            uint32_t so = (uint32_t)(r * 128 + ((g ^ (r & 7)) * 16));
            size_t goA = (size_t)(m0 + r) * (NF / 8) + kc * 8 + g;
            size_t goB = (size_t)(n0 + r) * (NF / 8) + kc * 8 + g;
            *(uint4*)(smem + SM_AH + so) = Ah4[goA];
            *(uint4*)(smem + SM_AL + so) = Al4[goA];
            *(uint4*)(smem + SM_BH + so) = Bh4[goB];
            *(uint4*)(smem + SM_BL + so) = Bl4[goB];
        }
        __syncthreads();

#pragma unroll
        for (int ks = 0; ks < 4; ks++) {
            const int gg = ks * 2 + lkh;
            uint32_t ahf[2][4], alf[2][4];
#pragma unroll
            for (int mt = 0; mt < 2; mt++) {
                int row = wy * 32 + mt * 16 + lrow;
                uint32_t off = (uint32_t)(row * 128 + ((gg ^ (row & 7)) * 16));
                ldsm_x4(sbase + SM_AH + off, ahf[mt][0], ahf[mt][1], ahf[mt][2], ahf[mt][3]);
                ldsm_x4(sbase + SM_AL + off, alf[mt][0], alf[mt][1], alf[mt][2], alf[mt][3]);
            }
#pragma unroll
            for (int btp = 0; btp < 4; btp++) {
                int row = wx * 64 + btp * 16 + lrow;
                uint32_t off = (uint32_t)(row * 128 + ((gg ^ (row & 7)) * 16));
                uint32_t h0, h1, h2, h3, l0, l1, l2, l3;
                ldsm_x4(sbase + SM_BH + off, h0, h1, h2, h3);
                ldsm_x4(sbase + SM_BL + off, l0, l1, l2, l3);
                uint32_t bfh[2][2] = {{h0, h2}, {h1, h3}};
                uint32_t bfl[2][2] = {{l0, l2}, {l1, l3}};
#pragma unroll
                for (int mt = 0; mt < 2; mt++)
#pragma unroll
                    for (int nn = 0; nn < 2; nn++) {
                        float* c = acc[mt][btp * 2 + nn];
                        mma16816(c, ahf[mt], bfh[nn]);
                        mma16816(c, ahf[mt], bfl[nn]);
                        mma16816(c, alf[mt], bfh[nn]);
                    }
            }
        }
        __syncthreads();
    }

#pragma unroll
    for (int mt = 0; mt < 2; mt++) {
        int mrow = m0 + wy * 32 + mt * 16 + (lane >> 2);
#pragma unroll
        for (int nt = 0; nt < 8; nt++) {
            int n = n0 + wx * 64 + nt * 8 + (lane & 3) * 2;
            float2 bv = *(const float2*)&bias[n];
            float2 v0, v1;
            v0.x = acc[mt][nt][0] + bv.x;
            v0.y = acc[mt][nt][1] + bv.y;
            v1.x = acc[mt][nt][2] + bv.x;
            v1.y = acc[mt][nt][3] + bv.y;
            if (mode == 0) {
                *(float2*)&C[(size_t)mrow * NF + n] = v0;
                *(float2*)&C[(size_t)(mrow + 8) * NF + n] = v1;
            } else {
                int h = n >> 6, d = n & 63;
                uint32_t hh, ll;
                int b = mrow >> 11, l = mrow & 2047;
                size_t o0 = (((size_t)(b * NHEAD + h)) * LSEQ + l) * DK + d;
                split2(v0.x, v0.y, hh, ll);
                *(uint32_t*)&Ch[o0] = hh;
                *(uint32_t*)&Cl[o0] = ll;
                int b2 = (mrow + 8) >> 11, l2v = (mrow + 8) & 2047;
                size_t o1 = (((size_t)(b2 * NHEAD + h)) * LSEQ + l2v) * DK + d;
                split2(v1.x, v1.y, hh, ll);
                *(uint32_t*)&Ch[o1] = hh;
                *(uint32_t*)&Cl[o1] = ll;
            }
        }
    }
}

// ---------------------------------------------------------------------------
// Flash attention via mma.sync, split-bf16 3-term on both phases.
// CTA: 128 queries x one (b,h). 8 warps; warp w owns query rows w*16..w*16+15.
// K-tiles of 64 keys. Smem: Q hi/lo [128][64], K hi/lo [64][64], V hi/lo
// [64][64] (natural [key][d]; B-frags via ldmatrix.trans). All bf16, 128B
// rows, XOR-granule swizzle.
// ---------------------------------------------------------------------------
#define SQH 0
#define SQL 16384
#define SKH 32768
#define SKL 40960
#define SVH 49152
#define SVL 57344
#define ATTN_SMEM 65536

__global__ __launch_bounds__(256) void attn_mma(
    const __nv_bfloat16* __restrict__ Qh, const __nv_bfloat16* __restrict__ Ql,
    const __nv_bfloat16* __restrict__ Kh, const __nv_bfloat16* __restrict__ Kl,
    const __nv_bfloat16* __restrict__ Vh, const __nv_bfloat16* __restrict__ Vl,
    __nv_bfloat16* __restrict__ Xh, __nv_bfloat16* __restrict__ Xl)
{
    extern __shared__ char smem[];
    const uint32_t sbase = smem_u32(smem);

    const int tid = threadIdx.x;
    const int lane = tid & 31;
    const int wid = tid >> 5;          // 0..7
    const int qt = blockIdx.x;         // 0..15
    const int bh = blockIdx.y;         // 0..63
    const int lrow = lane & 15;
    const int lkh  = lane >> 4;

    // ---- load Q tile (128x64 hi/lo) ----
    {
        const uint4* Qh4 = (const uint4*)(Qh + ((size_t)bh * LSEQ + qt * 128) * DK);
        const uint4* Ql4 = (const uint4*)(Ql + ((size_t)bh * LSEQ + qt * 128) * DK);
#pragma unroll
        for (int it = 0; it < 4; it++) {
            int idx = tid + 256 * it;
            int r = idx >> 3, g = idx & 7;
            uint32_t so = (uint32_t)(r * 128 + ((g ^ (r & 7)) * 16));
            *(uint4*)(smem + SQH + so) = Qh4[r * 8 + g];
            *(uint4*)(smem + SQL + so) = Ql4[r * 8 + g];
        }
    }
    __syncthreads();

    // ---- Q fragments, held in registers for whole kernel ----
    uint32_t qhf[4][4], qlf[4][4];
#pragma unroll
    for (int ks = 0; ks < 4; ks++) {
        int gg = ks * 2 + lkh;
        int row = wid * 16 + lrow;
        uint32_t off = (uint32_t)(row * 128 + ((gg ^ (row & 7)) * 16));
        ldsm_x4(sbase + SQH + off, qhf[ks][0], qhf[ks][1], qhf[ks][2], qhf[ks][3]);
        ldsm_x4(sbase + SQL + off, qlf[ks][0], qlf[ks][1], qlf[ks][2], qlf[ks][3]);
    }

    float m_[2] = {-1e30f, -1e30f};
    float l_[2] = {0.f, 0.f};
    float o[8][4];
#pragma unroll
    for (int t = 0; t < 8; t++)
#pragma unroll
        for (int q = 0; q < 4; q++) o[t][q] = 0.f;

    const __nv_bfloat16* Kh_b = Kh + (size_t)bh * LSEQ * DK;
    const __nv_bfloat16* Kl_b = Kl + (size_t)bh * LSEQ * DK;
    const __nv_bfloat16* Vh_b = Vh + (size_t)bh * LSEQ * DK;
    const __nv_bfloat16* Vl_b = Vl + (size_t)bh * LSEQ * DK;

    for (int kt = 0; kt < LSEQ / 64; kt++) {
        __syncthreads();   // previous iteration's reads done
        // ---- load K/V tiles (64x64 hi/lo each) ----
        {
            const uint4* KH4 = (const uint4*)(Kh_b + (size_t)kt * 64 * DK);
            const uint4* KL4 = (const uint4*)(Kl_b + (size_t)kt * 64 * DK);
            const uint4* VH4 = (const uint4*)(Vh_b + (size_t)kt * 64 * DK);
            const uint4* VL4 = (const uint4*)(Vl_b + (size_t)kt * 64 * DK);
#pragma unroll
            for (int it = 0; it < 2; it++) {
                int idx = tid + 256 * it;     // 0..511
                int r = idx >> 3, g = idx & 7;
                uint32_t so = (uint32_t)(r * 128 + ((g ^ (r & 7)) * 16));
                *(uint4*)(smem + SKH + so) = KH4[r * 8 + g];
                *(uint4*)(smem + SKL + so) = KL4[r * 8 + g];
                *(uint4*)(smem + SVH + so) = VH4[r * 8 + g];
                *(uint4*)(smem + SVL + so) = VL4[r * 8 + g];
            }
        }
        __syncthreads();

        // ---- S = Q K^T (3-term split) ----
        float s[8][4];
#pragma unroll
        for (int t = 0; t < 8; t++)
#pragma unroll
            for (int q = 0; q < 4; q++) s[t][q] = 0.f;

#pragma unroll
        for (int ks = 0; ks < 4; ks++) {
            int gg = ks * 2 + lkh;
#pragma unroll
            for (int btp = 0; btp < 4; btp++) {
                int row = btp * 16 + lrow;
                uint32_t off = (uint32_t)(row * 128 + ((gg ^ (row & 7)) * 16));
                uint32_t h0, h1, h2, h3, l0, l1, l2, l3;
                ldsm_x4(sbase + SKH + off, h0, h1, h2, h3);
                ldsm_x4(sbase + SKL + off, l0, l1, l2, l3);
                uint32_t bfh[2][2] = {{h0, h2}, {h1, h3}};
                uint32_t bfl[2][2] = {{l0, l2}, {l1, l3}};
#pragma unroll
                for (int nn = 0; nn < 2; nn++) {
                    float* c = s[btp * 2 + nn];
                    mma16816(c, qhf[ks], bfh[nn]);
                    mma16816(c, qhf[ks], bfl[nn]);
                    mma16816(c, qlf[ks], bfh[nn]);
                }
            }
        }

        // ---- online softmax (rows r_lo: elems 0,1; r_hi: elems 2,3) ----
        float mx0 = -1e30f, mx1 = -1e30f;
#pragma unroll
        for (int t = 0; t < 8; t++) {
            s[t][0] *= 0.125f; s[t][1] *= 0.125f;
            s[t][2] *= 0.125f; s[t][3] *= 0.125f;
            mx0 = fmaxf(mx0, fmaxf(s[t][0], s[t][1]));
            mx1 = fmaxf(mx1, fmaxf(s[t][2], s[t][3]));
        }
        mx0 = fmaxf(mx0, __shfl_xor_sync(0xffffffffu, mx0, 1));
        mx0 = fmaxf(mx0, __shfl_xor_sync(0xffffffffu, mx0, 2));
        mx1 = fmaxf(mx1, __shfl_xor_sync(0xffffffffu, mx1, 1));
        mx1 = fmaxf(mx1, __shfl_xor_sync(0xffffffffu, mx1, 2));
        float mn0 = fmaxf(m_[0], mx0), mn1 = fmaxf(m_[1], mx1);
        float c0 = __expf(m_[0] - mn0), c1 = __expf(m_[1] - mn1);
        m_[0] = mn0; m_[1] = mn1;
        float sum0 = 0.f, sum1 = 0.f;
#pragma unroll
        for (int t = 0; t < 8; t++) {
            s[t][0] = __expf(s[t][0] - mn0);
            s[t][1] = __expf(s[t][1] - mn0);
            s[t][2] = __expf(s[t][2] - mn1);
            s[t][3] = __expf(s[t][3] - mn1);
            sum0 += s[t][0] + s[t][1];
            sum1 += s[t][2] + s[t][3];
        }
        sum0 += __shfl_xor_sync(0xffffffffu, sum0, 1);
        sum0 += __shfl_xor_sync(0xffffffffu, sum0, 2);
        sum1 += __shfl_xor_sync(0xffffffffu, sum1, 1);
        sum1 += __shfl_xor_sync(0xffffffffu, sum1, 2);
        l_[0] = l_[0] * c0 + sum0;
        l_[1] = l_[1] * c1 + sum1;
#pragma unroll
        for (int t = 0; t < 8; t++) {
            o[t][0] *= c0; o[t][1] *= c0;
            o[t][2] *= c1; o[t][3] *= c1;
        }

        // ---- O += P V (3-term split); P packed from S regs in place ----
#pragma unroll
        for (int kt2 = 0; kt2 < 4; kt2++) {
            uint32_t pah[4], pal[4];
            split2(s[2 * kt2][0],     s[2 * kt2][1],     pah[0], pal[0]);
            split2(s[2 * kt2][2],     s[2 * kt2][3],     pah[1], pal[1]);
            split2(s[2 * kt2 + 1][0], s[2 * kt2 + 1][1], pah[2], pal[2]);
            split2(s[2 * kt2 + 1][2], s[2 * kt2 + 1][3], pah[3], pal[3]);
#pragma unroll
            for (int jp = 0; jp < 4; jp++) {
                int row = kt2 * 16 + lrow;
                int g = jp * 2 + lkh;
                uint32_t off = (uint32_t)(row * 128 + ((g ^ (row & 7)) * 16));
                uint32_t vh0, vh1, vh2, vh3, vl0, vl1, vl2, vl3;
                ldsm_x4_t(sbase + SVH + off, vh0, vh1, vh2, vh3);
                ldsm_x4_t(sbase + SVL + off, vl0, vl1, vl2, vl3);
                uint32_t bh0[2] = {vh0, vh1}, bh1[2] = {vh2, vh3};
                uint32_t bl0[2] = {vl0, vl1}, bl1[2] = {vl2, vl3};
                float* c0p = o[jp * 2];
                float* c1p = o[jp * 2 + 1];
                mma16816(c0p, pah, bh0);
                mma16816(c0p, pah, bl0);
                mma16816(c0p, pal, bh0);
                mma16816(c1p, pah, bh1);
                mma16816(c1p, pah, bl1);
                mma16816(c1p, pal, bh1);
            }
        }
    }

    // ---- epilogue: normalize, split to bf16 hi/lo, write X[b][l][h*64+d] ----
    const int b = bh >> 4, h = bh & 15;
    float inv0 = 1.f / l_[0], inv1 = 1.f / l_[1];
    int row0 = qt * 128 + wid * 16 + (lane >> 2);
    int row1 = row0 + 8;
    int colb = h * DK + (lane & 3) * 2;
#pragma unroll
    for (int j = 0; j < 8; j++) {
        uint32_t hh, ll;
        size_t o0 = ((size_t)b * LSEQ + row0) * NF + colb + j * 8;
        split2(o[j][0] * inv0, o[j][1] * inv0, hh, ll);
        *(uint32_t*)&Xh[o0] = hh;
        *(uint32_t*)&Xl[o0] = ll;
        size_t o1 = ((size_t)b * LSEQ + row1) * NF + colb + j * 8;
        split2(o[j][2] * inv1, o[j][3] * inv1, hh, ll);
        *(uint32_t*)&Xh[o1] = hh;
        *(uint32_t*)&Xl[o1] = ll;
    }
}

// ---------------------------------------------------------------------------
extern "C" void kernel_launch(void* const* d_in, const int* in_sizes, int n_in,
                              void* d_out, int out_size)
{
    const float* query = (const float*)d_in[0];
    const float* key   = (const float*)d_in[1];
    const float* value = (const float*)d_in[2];
    const float* Wq    = (const float*)d_in[3];
    const float* bq    = (const float*)d_in[4];
    const float* Wk    = (const float*)d_in[5];
    const float* bk    = (const float*)d_in[6];
    const float* Wv    = (const float*)d_in[7];
    const float* bv    = (const float*)d_in[8];
    const float* Wo    = (const float*)d_in[9];
    const float* bo    = (const float*)d_in[10];
    float* out = (float*)d_out;

    __nv_bfloat16 *qh, *ql, *kh, *kl, *vh, *vl, *ah, *al, *wh, *wl;
    cudaGetSymbolAddress((void**)&qh, g_qh);
    cudaGetSymbolAddress((void**)&ql, g_ql);
    cudaGetSymbolAddress((void**)&kh, g_kh);
    cudaGetSymbolAddress((void**)&kl, g_kl);
    cudaGetSymbolAddress((void**)&vh, g_vh);
    cudaGetSymbolAddress((void**)&vl, g_vl);
    cudaGetSymbolAddress((void**)&ah, g_ah);
    cudaGetSymbolAddress((void**)&al, g_al);
    cudaGetSymbolAddress((void**)&wh, g_wh);
    cudaGetSymbolAddress((void**)&wl, g_wl);

    cudaFuncSetAttribute(gemm_mma,
                         cudaFuncAttributeMaxDynamicSharedMemorySize, GEMM_SMEM);
    cudaFuncSetAttribute(attn_mma,
                         cudaFuncAttributeMaxDynamicSharedMemorySize, ATTN_SMEM);

    const int n4 = MTOT * NF / 4;
    const int split_blocks = (n4 + 255) / 256;
    dim3 wt_grid(NF / 32, NF / 32), wt_block(32, 8);
    dim3 gemm_grid(NF / 128, MTOT / 128);

    // Q projection -> bf16 hi/lo per-head layout
    split_act<<<split_blocks, 256>>>(query, (__nv_bfloat162*)ah, (__nv_bfloat162*)al, n4);
    split_wT<<<wt_grid, wt_block>>>(Wq, wh, wl);
    gemm_mma<<<gemm_grid, 256, GEMM_SMEM>>>(ah, al, wh, wl, bq, nullptr, qh, ql, 1);
    // K projection
    split_act<<<split_blocks, 256>>>(key, (__nv_bfloat162*)ah, (__nv_bfloat162*)al, n4);
    split_wT<<<wt_grid, wt_block>>>(Wk, wh, wl);
    gemm_mma<<<gemm_grid, 256, GEMM_SMEM>>>(ah, al, wh, wl, bk, nullptr, kh, kl, 1);
    // V projection
    split_act<<<split_blocks, 256>>>(value, (__nv_bfloat162*)ah, (__nv_bfloat162*)al, n4);
    split_wT<<<wt_grid, wt_block>>>(Wv, wh, wl);
    gemm_mma<<<gemm_grid, 256, GEMM_SMEM>>>(ah, al, wh, wl, bv, nullptr, vh, vl, 1);

    // attention: writes split X directly into activation buffers
    dim3 attn_grid(LSEQ / 128, BATCH * NHEAD);
    attn_mma<<<attn_grid, 256, ATTN_SMEM>>>(qh, ql, kh, kl, vh, vl, ah, al);

    // output projection (fp32 out)
    split_wT<<<wt_grid, wt_block>>>(Wo, wh, wl);
    gemm_mma<<<gemm_grid, 256, GEMM_SMEM>>>(ah, al, wh, wl, bo, out, nullptr, nullptr, 0);
}